// round 15
// baseline (speedup 1.0000x reference)
#include <cuda_runtime.h>
#include <cstdint>

// SINDy library: out[row] = [1, z(32), z_i*z_j (528), z_a*z_b*z_c (5984), sin(z)(32)]
// 8192 rows x 6577 cols fp32.
// R15 = R14 (single-barrier prologue, 4-wide branchless groups via fixup-redirect,
// unroll-2, one STG.128 per chain) with TWO shifted buf copies + 2x LDS.64 reads
// (same L1 wavefronts as LDS.128, but halves the prologue's copy-replication STS).

#define NDIM     32
#define NPAIRS   528
#define NCOLS    6577
#define SBUF_PAD 600
#define NTHREADS 256
#define FIXBASE  (2 * SBUF_PAD)       // float idx of fixup region; 4800 B -> 16B aligned
#define FIX_MAX  320
#define SALL_N   (FIXBASE + FIX_MAX)
#define TB_PAD   2200                 // >= max ng4 (1644) + 2*NTHREADS pad

static constexpr int pair_index(int i, int j) {
    return i * NDIM - (i * (i - 1)) / 2 + (j - i);
}

// ---- per-column (k, a): value = s_mul[a] * buf[k]; a=32 -> 1.0 ----
struct ColTbl { unsigned short e[NCOLS]; };
static constexpr ColTbl make_col_tbl() {
    ColTbl t{};
    for (int c = 0; c < 561; ++c)
        t.e[c] = (unsigned short)((unsigned)c | (32u << 10));
    {
        int col = 561;
        for (int a = 0; a < NDIM; ++a)
            for (int b = a; b < NDIM; ++b)
                for (int c = b; c < NDIM; ++c) {
                    unsigned k = 33u + (unsigned)pair_index(b, c);
                    t.e[col++] = (unsigned short)(k | ((unsigned)a << 10));
                }
    }
    for (int i = 0; i < NDIM; ++i)
        t.e[6545 + i] = (unsigned short)((unsigned)(561 + i) | (32u << 10));
    return t;
}
__device__ constexpr ColTbl G_COL = make_col_tbl();

// ---- per-column decomposition: factors m in [0,32]=z/1.0, [33,64]=sin ----
static constexpr unsigned col_m3(int c) {
    if (c == 0)   return 32u | (32u << 7) | (32u << 14);
    if (c < 33)   return (unsigned)(c - 1) | (32u << 7) | (32u << 14);
    if (c < 561) {
        int p = c - 33, i = 0;
        while (p >= NDIM - i) { p -= NDIM - i; ++i; }
        return (unsigned)i | ((unsigned)(i + p) << 7) | (32u << 14);
    }
    if (c < 6545) {
        int r = c - 561, a = 0;
        while (true) {
            int m = NDIM - a, cnt = m * (m + 1) / 2;
            if (r < cnt) break;
            r -= cnt; ++a;
        }
        int b = a;
        while (r >= NDIM - b) { r -= NDIM - b; ++b; }
        return (unsigned)a | ((unsigned)b << 7) | ((unsigned)(b + r) << 14);
    }
    return (unsigned)(33 + (c - 6545)) | (32u << 7) | (32u << 14);
}

// ---- 4-wide group table with fixup redirection, per phase ----
// Entry low16: byte offset into s_all of an 8B-ALIGNED float2 pair base
// (copy P = k0&1, idx = k0+P); bits[16..30): za byte offset into s_mul.
struct Tbl4 {
    unsigned e[4][TB_PAD];
    unsigned fixsrc[4][FIX_MAX];
    int      ng[4];
    int      nfix[4];
};

static constexpr Tbl4 make_tbl4() {
    ColTbl ct = make_col_tbl();
    Tbl4 t{};
    for (int ph = 0; ph < 4; ++ph) {
        int ng = (NCOLS - ph) / 4;
        t.ng[ph] = ng;
        int nf = 0;
        for (int g = 0; g < ng; ++g) {
            int c0 = ph + 4 * g;
            unsigned k0 = ct.e[c0] & 1023u;
            unsigned a0 = (unsigned)(ct.e[c0] >> 10);
            bool uniform = true;
            for (int j = 1; j < 4; ++j) {
                unsigned kj = ct.e[c0 + j] & 1023u;
                unsigned aj = (unsigned)(ct.e[c0 + j] >> 10);
                if (kj != k0 + (unsigned)j || aj != a0) { uniform = false; break; }
            }
            if (uniform) {
                unsigned P   = k0 & 1u;
                unsigned off = (P * SBUF_PAD + k0 + P) * 4u;  // 8B aligned
                t.e[ph][g] = off | ((a0 * 4u) << 16);
            } else {
                unsigned off = (unsigned)(FIXBASE + nf) * 4u; // 16B aligned region
                t.e[ph][g] = off | ((32u * 4u) << 16);
                for (int j = 0; j < 4; ++j)
                    t.fixsrc[ph][nf++] = col_m3(c0 + j);
            }
        }
        t.nfix[ph] = nf;
        for (int g = ng; g < TB_PAD; ++g) t.e[ph][g] = 0;
        for (int i = nf; i < FIX_MAX; ++i) t.fixsrc[ph][i] = 32u | (32u << 7) | (32u << 14);
    }
    return t;
}
__device__ constexpr Tbl4 G4 = make_tbl4();

struct PairTbl { unsigned short e[NPAIRS]; };
static constexpr PairTbl make_pair_tbl() {
    PairTbl t{};
    int p = 0;
    for (int i = 0; i < NDIM; ++i)
        for (int j = i; j < NDIM; ++j)
            t.e[p++] = (unsigned short)((unsigned)i | ((unsigned)j << 8));
    return t;
}
__device__ constexpr PairTbl G_PAIR = make_pair_tbl();

// Factor fetch straight from global z (L1-hot line); m: 0-31 z, 32 -> 1.0, 33-64 sin.
__device__ __forceinline__ float fac(const float* __restrict__ zr, unsigned m) {
    if (m < 32u)  return __ldg(zr + m);
    if (m == 32u) return 1.0f;
    return __sinf(__ldg(zr + (m - 33u)));
}

__global__ __launch_bounds__(NTHREADS, 8) void sindy_library_kernel(
    const float* __restrict__ z, float* __restrict__ out)
{
    // s_all: 2 shifted copies (copy P at P*SBUF_PAD; s_copyP[P+k] = buf[k]) +
    // fixup region at FIXBASE. float2 reads at (k0+P), P=k0&1: 8B-aligned.
    __shared__ __align__(16) float s_all[SALL_N];
    __shared__ float s_mul[NDIM + 1];   // z..., 1.0f at [32]

    const int row = blockIdx.x;
    const int t   = threadIdx.x;
    const int ph  = (4 - (row & 3)) & 3;
    const float* __restrict__ zr = z + (size_t)row * NDIM;

    // ---- single-barrier prologue: three independent build tasks ----
    if (t < NDIM) {
        float v  = __ldg(zr + t);
        float sv = __sinf(v);
        s_mul[t] = v;
        #pragma unroll
        for (int P = 0; P < 2; ++P) {
            s_all[P * SBUF_PAD + P + 1 + t]   = v;
            s_all[P * SBUF_PAD + P + 561 + t] = sv;
        }
    } else if (t == NDIM) {
        s_mul[NDIM] = 1.0f;
        #pragma unroll
        for (int P = 0; P < 2; ++P) s_all[P * SBUF_PAD + P] = 1.0f;
    }

    for (int p = t; p < NPAIRS; p += NTHREADS) {
        unsigned ij = (unsigned)G_PAIR.e[p];
        float v = __ldg(zr + (ij & 31u)) * __ldg(zr + ((ij >> 8) & 31u));
        #pragma unroll
        for (int P = 0; P < 2; ++P) s_all[P * SBUF_PAD + P + 33 + p] = v;
    }

    {
        const int nfix = G4.nfix[ph];
        for (int f = t; f < nfix; f += NTHREADS) {
            unsigned s = __ldg(&G4.fixsrc[ph][f]);
            s_all[FIXBASE + f] =
                fac(zr, s & 127u) * fac(zr, (s >> 7) & 127u) * fac(zr, (s >> 14) & 127u);
        }
    }
    __syncthreads();   // the only block-wide barrier

    float* __restrict__ o = out + (size_t)row * NCOLS;

    // Head scalars (< 4 cols)
    if (t < ph) {
        unsigned e = (unsigned)G_COL.e[t];
        o[t] = s_mul[e >> 10] * s_all[e & 1023u];
    }

    const int ng = G4.ng[ph];
    const unsigned* __restrict__ tb = &G4.e[ph][0];
    const char* __restrict__ sc = (const char*)&s_all[0];
    const char* __restrict__ sm = (const char*)&s_mul[0];

    // 2x-unrolled main loop: two independent chains, each 2xLDS.64 + STG.128.
    unsigned e0 = __ldg(&tb[t]);
    unsigned e1 = __ldg(&tb[t + NTHREADS]);
    int g = t;
    for (; g + NTHREADS < ng; g += 2 * NTHREADS) {
        unsigned f0 = __ldg(&tb[g + 2 * NTHREADS]);   // padded: in-bounds
        unsigned f1 = __ldg(&tb[g + 3 * NTHREADS]);

        float2 b0a = *(const float2*)(sc + (e0 & 0xFFFFu));
        float2 b0b = *(const float2*)(sc + (e0 & 0xFFFFu) + 8);
        float2 b1a = *(const float2*)(sc + (e1 & 0xFFFFu));
        float2 b1b = *(const float2*)(sc + (e1 & 0xFFFFu) + 8);
        float  za0 = *(const float*)(sm + (e0 >> 16));
        float  za1 = *(const float*)(sm + (e1 >> 16));

        float4 r0 = make_float4(za0 * b0a.x, za0 * b0a.y, za0 * b0b.x, za0 * b0b.y);
        __stcs((float4*)(o + ph + 4 * g), r0);

        float4 r1 = make_float4(za1 * b1a.x, za1 * b1a.y, za1 * b1b.x, za1 * b1b.y);
        __stcs((float4*)(o + ph + 4 * (g + NTHREADS)), r1);

        e0 = f0;
        e1 = f1;
    }
    if (g < ng) {
        float2 ba = *(const float2*)(sc + (e0 & 0xFFFFu));
        float2 bb = *(const float2*)(sc + (e0 & 0xFFFFu) + 8);
        float  za = *(const float*)(sm + (e0 >> 16));
        float4 r  = make_float4(za * ba.x, za * ba.y, za * bb.x, za * bb.y);
        __stcs((float4*)(o + ph + 4 * g), r);
    }

    // Tail scalars (< 4 cols)
    {
        int c = ph + 4 * ng + t;
        if (c < NCOLS) {
            unsigned ee = (unsigned)G_COL.e[c];
            o[c] = s_mul[ee >> 10] * s_all[ee & 1023u];
        }
    }
}

extern "C" void kernel_launch(void* const* d_in, const int* in_sizes, int n_in,
                              void* d_out, int out_size) {
    const float* z   = (const float*)d_in[0];
    float*       out = (float*)d_out;
    sindy_library_kernel<<<8192, NTHREADS>>>(z, out);
}